// round 5
// baseline (speedup 1.0000x reference)
#include <cuda_runtime.h>
#include <cstdint>

// Shapes fixed by the problem: B=4, S=512, V=32000, S_pen=128.
#define B_DIM 4
#define S_DIM 512
#define V_DIM 32000
#define MASK_STRIDE 1024     // padded words per batch (need ceil(32000/32)=1000)

// Presence bitmask: bit v of g_mask[b*MASK_STRIDE + v/32] == 1 iff v appears
// in penalty_sequence[b,:] with v != pad_id. 16 KB total -> L2-resident.
__device__ unsigned int g_mask[B_DIM * MASK_STRIDE];

// Single-block mask builder with on-device dtype sniffing.
// JAX (x64 disabled) materializes the declared-int64 penalty_sequence as
// int32 — handle both: for little-endian int64 ids < 32000, every odd 32-bit
// word is 0; for int32 random ids that is (1/32000)^256 ~ impossible.
__global__ void build_mask_kernel(const unsigned int* __restrict__ pen32,
                                  int pen_count,            // element count (B*S_pen)
                                  const int* __restrict__ pad_ptr) {
    const int tid = threadIdx.x;
    for (int i = tid; i < B_DIM * MASK_STRIDE; i += blockDim.x)
        g_mask[i] = 0u;

    __shared__ int odd_nonzero;
    if (tid == 0) odd_nonzero = 0;
    __syncthreads();

    for (int j = 1 + 2 * tid; j < pen_count; j += 2 * blockDim.x) {
        if (pen32[j] != 0u) { odd_nonzero = 1; break; }
    }
    __syncthreads();
    const bool is32 = (odd_nonzero != 0);

    const int pad = pad_ptr ? pad_ptr[0] : 0;   // low 32 bits, LE-safe
    const int per_b = pen_count / B_DIM;
    for (int i = tid; i < pen_count; i += blockDim.x) {
        const int id = is32 ? (int)pen32[i] : (int)pen32[2 * i];
        if (id != pad && (unsigned)id < (unsigned)V_DIM) {
            const int b = i / per_b;
            atomicOr(&g_mask[b * MASK_STRIDE + (id >> 5)], 1u << (id & 31));
        }
    }
}

// One CTA per TWO adjacent (b,s) rows (same batch -> same mask).
// grid = 1024 CTAs -> exactly one full wave at occ 8 on 148 SMs.
// Two independent row streams per thread double memory-level parallelism.
__global__ __launch_bounds__(256, 8)
void suppression_loss_kernel(const float4* __restrict__ logits,
                             float* __restrict__ out) {
    const int r0 = blockIdx.x * 2;         // rows r0, r0+1; same batch (S even)
    const int b  = r0 >> 9;                // / S_DIM
    const float4* __restrict__ p0 = logits + (size_t)r0 * (V_DIM / 4);
    const float4* __restrict__ p1 = p0 + (V_DIM / 4);
    const unsigned int* __restrict__ mask = g_mask + b * MASK_STRIDE;

    float s0 = 0.0f, t0 = 0.0f;   // row r0: denom, masked num
    float s1 = 0.0f, t1 = 0.0f;   // row r0+1

    #pragma unroll 2
    for (int i = threadIdx.x; i < V_DIM / 4; i += 256) {
        const float4 x = __ldg(p0 + i);
        const float4 y = __ldg(p1 + i);
        // vocab index v = 4*i ; mask word = v>>5 = i>>3 ; bit base = 4*(i&7)
        const unsigned int w = mask[i >> 3];
        const int sh = (i & 7) << 2;

        const float a0 = __expf(x.x), a1 = __expf(x.y);
        const float a2 = __expf(x.z), a3 = __expf(x.w);
        const float b0 = __expf(y.x), b1 = __expf(y.y);
        const float b2 = __expf(y.z), b3 = __expf(y.w);
        s0 += (a0 + a1) + (a2 + a3);
        s1 += (b0 + b1) + (b2 + b3);
        if ((w >> (sh + 0)) & 1u) { t0 += a0; t1 += b0; }
        if ((w >> (sh + 1)) & 1u) { t0 += a1; t1 += b1; }
        if ((w >> (sh + 2)) & 1u) { t0 += a2; t1 += b2; }
        if ((w >> (sh + 3)) & 1u) { t0 += a3; t1 += b3; }
    }

    // Block reduction: warp shuffle then smem across 8 warps.
    const int lane = threadIdx.x & 31;
    const int wid  = threadIdx.x >> 5;
    #pragma unroll
    for (int off = 16; off; off >>= 1) {
        s0 += __shfl_xor_sync(0xffffffffu, s0, off);
        t0 += __shfl_xor_sync(0xffffffffu, t0, off);
        s1 += __shfl_xor_sync(0xffffffffu, s1, off);
        t1 += __shfl_xor_sync(0xffffffffu, t1, off);
    }
    __shared__ float sm[4][8];
    if (lane == 0) { sm[0][wid] = s0; sm[1][wid] = t0; sm[2][wid] = s1; sm[3][wid] = t1; }
    __syncthreads();
    if (wid == 0) {
        s0 = (lane < 8) ? sm[0][lane] : 0.0f;
        t0 = (lane < 8) ? sm[1][lane] : 0.0f;
        s1 = (lane < 8) ? sm[2][lane] : 0.0f;
        t1 = (lane < 8) ? sm[3][lane] : 0.0f;
        #pragma unroll
        for (int off = 4; off; off >>= 1) {
            s0 += __shfl_xor_sync(0xffffffffu, s0, off);
            t0 += __shfl_xor_sync(0xffffffffu, t0, off);
            s1 += __shfl_xor_sync(0xffffffffu, s1, off);
            t1 += __shfl_xor_sync(0xffffffffu, t1, off);
        }
        if (lane == 0) {
            out[r0]     = t0 / s0;
            out[r0 + 1] = t1 / s1;
        }
    }
}

extern "C" void kernel_launch(void* const* d_in, const int* in_sizes, int n_in,
                              void* d_out, int out_size) {
    // Identify inputs by element count, not by position:
    //   logits:           B*S*V = 65,536,000 elements (largest)
    //   penalty_sequence: B*S_pen = 512 elements
    //   pad_id:           1 element (may be absent)
    int li = 0;
    long long mx = -1;
    for (int i = 0; i < n_in; i++) {
        if ((long long)in_sizes[i] > mx) { mx = in_sizes[i]; li = i; }
    }
    int si = -1, pi = -1;
    for (int i = 0; i < n_in; i++) {
        if (i == li) continue;
        if (in_sizes[i] == 1 && si < 0) si = i;
        else if (pi < 0) pi = i;
    }
    if (pi < 0) pi = (si >= 0 && si != li) ? si : li;  // degenerate fallback

    const float*        logits = (const float*)d_in[li];
    const unsigned int* pen32  = (const unsigned int*)d_in[pi];
    const int*          pad    = (si >= 0) ? (const int*)d_in[si] : nullptr;
    float*              out    = (float*)d_out;

    build_mask_kernel<<<1, 512>>>(pen32, in_sizes[pi], pad);
    suppression_loss_kernel<<<(B_DIM * S_DIM) / 2, 256>>>((const float4*)logits, out);
}